// round 13
// baseline (speedup 1.0000x reference)
#include <cuda_runtime.h>
#include <cuda_bf16.h>
#include <cstdint>

#define B_ 2048
#define T_ 256
#define F_ 64
#define H_ 32
#define G_ 96

// scratch: xg[B*T][96] fp32 (201 MB)
__device__ float g_xg[(size_t)B_ * T_ * G_];

__device__ __forceinline__ float tanh_fast(float v) {
    float y; asm("tanh.approx.f32 %0, %1;" : "=f"(y) : "f"(v)); return y;
}
__device__ __forceinline__ float sigmoid_fast(float a) {
    return fmaf(tanh_fast(0.5f * a), 0.5f, 0.5f);
}
__device__ __forceinline__ uint64_t ffma2(uint64_t a, uint64_t b, uint64_t c) {
    uint64_t d;
    asm("fma.rn.f32x2 %0, %1, %2, %3;" : "=l"(d) : "l"(a), "l"(b), "l"(c));
    return d;
}
__device__ __forceinline__ float f2lo(uint64_t v) { return __uint_as_float((uint32_t)v); }
__device__ __forceinline__ float f2hi(uint64_t v) { return __uint_as_float((uint32_t)(v >> 32)); }
__device__ __forceinline__ uint32_t pack_bf16(float a, float b) {
    __nv_bfloat162 t = __floats2bfloat162_rn(a, b);
    return *reinterpret_cast<uint32_t*>(&t);
}

// ================= Phase 1: xg = x @ W_ih^T + b_ih  (mma.sync bf16, 3-pass split) ===========
#define PM 128
#define AROW 144
#define AH_OFF 0
#define AL_OFF (PM * AROW)
#define BH_OFF (2 * PM * AROW)
#define BL_OFF (BH_OFF + G_ * AROW)
#define SMEM_P1 (BL_OFF + G_ * AROW)
#define STRIDE_ST 100

__device__ __forceinline__ void mma_bf16(float* d, uint32_t a0, uint32_t a1, uint32_t a2,
                                         uint32_t a3, uint32_t b0, uint32_t b1) {
    asm("mma.sync.aligned.m16n8k16.row.col.f32.bf16.bf16.f32 "
        "{%0,%1,%2,%3}, {%4,%5,%6,%7}, {%8,%9}, {%0,%1,%2,%3};"
        : "+f"(d[0]), "+f"(d[1]), "+f"(d[2]), "+f"(d[3])
        : "r"(a0), "r"(a1), "r"(a2), "r"(a3), "r"(b0), "r"(b1));
}
__device__ __forceinline__ void split4(float4 v, uint2& hp, uint2& lp) {
    __nv_bfloat16 h0 = __float2bfloat16(v.x), h1 = __float2bfloat16(v.y);
    __nv_bfloat16 h2 = __float2bfloat16(v.z), h3 = __float2bfloat16(v.w);
    hp.x = pack_bf16(__bfloat162float(h0), __bfloat162float(h1));
    hp.y = pack_bf16(__bfloat162float(h2), __bfloat162float(h3));
    lp.x = pack_bf16(v.x - __bfloat162float(h0), v.y - __bfloat162float(h1));
    lp.y = pack_bf16(v.z - __bfloat162float(h2), v.w - __bfloat162float(h3));
}

__global__ __launch_bounds__(256, 3)
void proj_kernel(const float* __restrict__ x,
                 const float* __restrict__ W_ih,
                 const float* __restrict__ b_ih,
                 float* __restrict__ xg)
{
    extern __shared__ __align__(16) char dsm[];
    __shared__ __align__(16) float sbias[G_];

    const int tid  = threadIdx.x;
    const int wid  = tid >> 5;
    const int lane = tid & 31;
    const int g    = lane >> 2;
    const int tg   = lane & 3;
    const size_t base = (size_t)blockIdx.x * PM;

    {
        const float4* xin = reinterpret_cast<const float4*>(x + base * F_);
        #pragma unroll
        for (int it = 0; it < PM * F_ / 4 / 256; it++) {
            int i = tid + it * 256;
            float4 v = xin[i];
            int row = i >> 4, c4 = i & 15;
            uint2 hp, lp; split4(v, hp, lp);
            uint32_t off = row * AROW + c4 * 8;
            *reinterpret_cast<uint2*>(dsm + AH_OFF + off) = hp;
            *reinterpret_cast<uint2*>(dsm + AL_OFF + off) = lp;
        }
    }
    {
        const float4* win = reinterpret_cast<const float4*>(W_ih);
        #pragma unroll
        for (int it = 0; it < G_ * F_ / 4 / 256; it++) {
            int i = tid + it * 256;
            float4 v = win[i];
            int row = i >> 4, c4 = i & 15;
            uint2 hp, lp; split4(v, hp, lp);
            uint32_t off = row * AROW + c4 * 8;
            *reinterpret_cast<uint2*>(dsm + BH_OFF + off) = hp;
            *reinterpret_cast<uint2*>(dsm + BL_OFF + off) = lp;
        }
    }
    if (tid < G_) sbias[tid] = b_ih[tid];
    __syncthreads();

    const int m0 = wid * 16;
    float acc[12][4];
    #pragma unroll
    for (int n = 0; n < 12; n++)
        #pragma unroll
        for (int q = 0; q < 4; q++) acc[n][q] = 0.f;

    const uint32_t arow0 = (m0 + g) * AROW;
    const uint32_t arow1 = (m0 + g + 8) * AROW;

    #pragma unroll
    for (int k = 0; k < 4; k++) {
        const uint32_t c0 = (k * 16 + 2 * tg) * 2;
        const uint32_t c1 = c0 + 16;
        uint32_t ah0 = *reinterpret_cast<const uint32_t*>(dsm + AH_OFF + arow0 + c0);
        uint32_t ah1 = *reinterpret_cast<const uint32_t*>(dsm + AH_OFF + arow1 + c0);
        uint32_t ah2 = *reinterpret_cast<const uint32_t*>(dsm + AH_OFF + arow0 + c1);
        uint32_t ah3 = *reinterpret_cast<const uint32_t*>(dsm + AH_OFF + arow1 + c1);
        uint32_t al0 = *reinterpret_cast<const uint32_t*>(dsm + AL_OFF + arow0 + c0);
        uint32_t al1 = *reinterpret_cast<const uint32_t*>(dsm + AL_OFF + arow1 + c0);
        uint32_t al2 = *reinterpret_cast<const uint32_t*>(dsm + AL_OFF + arow0 + c1);
        uint32_t al3 = *reinterpret_cast<const uint32_t*>(dsm + AL_OFF + arow1 + c1);
        #pragma unroll
        for (int n = 0; n < 12; n++) {
            const uint32_t brow = (n * 8 + g) * AROW;
            uint32_t bh0 = *reinterpret_cast<const uint32_t*>(dsm + BH_OFF + brow + c0);
            uint32_t bh1 = *reinterpret_cast<const uint32_t*>(dsm + BH_OFF + brow + c1);
            uint32_t bl0 = *reinterpret_cast<const uint32_t*>(dsm + BL_OFF + brow + c0);
            uint32_t bl1 = *reinterpret_cast<const uint32_t*>(dsm + BL_OFF + brow + c1);
            mma_bf16(acc[n], ah0, ah1, ah2, ah3, bh0, bh1);
            mma_bf16(acc[n], ah0, ah1, ah2, ah3, bl0, bl1);
            mma_bf16(acc[n], al0, al1, al2, al3, bh0, bh1);
        }
    }
    __syncthreads();

    float* stage = reinterpret_cast<float*>(dsm);
    {
        #pragma unroll
        for (int n = 0; n < 12; n++) {
            int c = n * 8 + 2 * tg;
            float2* p0 = reinterpret_cast<float2*>(&stage[(m0 + g) * STRIDE_ST + c]);
            float2* p1 = reinterpret_cast<float2*>(&stage[(m0 + g + 8) * STRIDE_ST + c]);
            *p0 = make_float2(acc[n][0], acc[n][1]);
            *p1 = make_float2(acc[n][2], acc[n][3]);
        }
    }
    __syncthreads();

    {
        float4* outp = reinterpret_cast<float4*>(xg + base * G_);
        #pragma unroll
        for (int it = 0; it < PM * G_ / 4 / 256; it++) {
            int i = tid + it * 256;
            int e = 4 * i;
            int r = e / G_, c = e % G_;
            float4 bb = *reinterpret_cast<const float4*>(&sbias[c]);
            const float* sp = &stage[r * STRIDE_ST + c];
            float4 v;
            v.x = sp[0] + bb.x; v.y = sp[1] + bb.y;
            v.z = sp[2] + bb.z; v.w = sp[3] + bb.w;
            outp[i] = v;
        }
    }
}

// ================= Phase 2: recurrence (warp/row, 2-step register prefetch, f32x2) ==========
#define WARPS_P2 4

__global__ __launch_bounds__(32 * WARPS_P2, 4)
void gru_kernel(const float* __restrict__ xg,
                const float* __restrict__ W_hh,
                const float* __restrict__ b_hh,
                const float* __restrict__ W_head,
                const float* __restrict__ b_head,
                float* __restrict__ out)
{
    __shared__ __align__(16) float sh[WARPS_P2][2][H_];

    const int wid = threadIdx.x >> 5;
    const int j   = threadIdx.x & 31;
    const int row = blockIdx.x * WARPS_P2 + wid;

    // per-lane recurrent weights as f32x2 pairs
    uint64_t Wr2[H_ / 2], Wz2[H_ / 2], Wn2[H_ / 2];
    {
        const ulonglong2* pr = reinterpret_cast<const ulonglong2*>(W_hh + (j)          * H_);
        const ulonglong2* pz = reinterpret_cast<const ulonglong2*>(W_hh + (H_ + j)     * H_);
        const ulonglong2* pn = reinterpret_cast<const ulonglong2*>(W_hh + (2 * H_ + j) * H_);
        #pragma unroll
        for (int i = 0; i < H_ / 4; i++) {
            ulonglong2 a = pr[i], b = pz[i], c = pn[i];
            Wr2[2*i] = a.x; Wr2[2*i+1] = a.y;
            Wz2[2*i] = b.x; Wz2[2*i+1] = b.y;
            Wn2[2*i] = c.x; Wn2[2*i+1] = c.y;
        }
    }
    const uint64_t br2 = (uint64_t)__float_as_uint(b_hh[j]);
    const uint64_t bz2 = (uint64_t)__float_as_uint(b_hh[H_ + j]);
    const uint64_t bn2 = (uint64_t)__float_as_uint(b_hh[2 * H_ + j]);

    const float* xp = xg + (size_t)row * T_ * G_;

    // 2-step register prefetch pipeline (lead ~2 step-times >> DRAM latency)
    float xr0 = xp[j],            xz0 = xp[H_ + j],            xn0 = xp[2 * H_ + j];
    float xr1 = xp[G_ + j],       xz1 = xp[G_ + H_ + j],       xn1 = xp[G_ + 2 * H_ + j];

    sh[wid][0][j] = 0.f;
    float h = 0.f;
    __syncwarp();

    #pragma unroll 1
    for (int t = 0; t < T_; t += 2) {
        // ---------- step t (uses xr0; prefetch t+2) ----------
        {
            const float* xq = xp + (size_t)min(t + 2, T_ - 1) * G_;
            float pr = xq[j], pz = xq[H_ + j], pn = xq[2 * H_ + j];

            const ulonglong2* hp = reinterpret_cast<const ulonglong2*>(sh[wid][0]);
            uint64_t ar0 = br2, ar1 = 0ull;
            uint64_t az0 = bz2, az1 = 0ull;
            uint64_t an0 = bn2, an1 = 0ull;
            #pragma unroll
            for (int i = 0; i < H_ / 4; i++) {
                ulonglong2 hv = hp[i];
                ar0 = ffma2(hv.x, Wr2[2*i],   ar0);
                az0 = ffma2(hv.x, Wz2[2*i],   az0);
                an0 = ffma2(hv.x, Wn2[2*i],   an0);
                ar1 = ffma2(hv.y, Wr2[2*i+1], ar1);
                az1 = ffma2(hv.y, Wz2[2*i+1], az1);
                an1 = ffma2(hv.y, Wn2[2*i+1], an1);
            }
            float arf = (f2lo(ar0) + f2hi(ar0)) + (f2lo(ar1) + f2hi(ar1));
            float azf = (f2lo(az0) + f2hi(az0)) + (f2lo(az1) + f2hi(az1));
            float anf = (f2lo(an0) + f2hi(an0)) + (f2lo(an1) + f2hi(an1));

            float r = sigmoid_fast(xr0 + arf);
            float z = sigmoid_fast(xz0 + azf);
            float n = tanh_fast(fmaf(r, anf, xn0));
            h = fmaf(z, h - n, n);
            sh[wid][1][j] = h;
            xr0 = pr; xz0 = pz; xn0 = pn;
            __syncwarp();
        }
        // ---------- step t+1 (uses xr1; prefetch t+3) ----------
        {
            const float* xq = xp + (size_t)min(t + 3, T_ - 1) * G_;
            float pr = xq[j], pz = xq[H_ + j], pn = xq[2 * H_ + j];

            const ulonglong2* hp = reinterpret_cast<const ulonglong2*>(sh[wid][1]);
            uint64_t ar0 = br2, ar1 = 0ull;
            uint64_t az0 = bz2, az1 = 0ull;
            uint64_t an0 = bn2, an1 = 0ull;
            #pragma unroll
            for (int i = 0; i < H_ / 4; i++) {
                ulonglong2 hv = hp[i];
                ar0 = ffma2(hv.x, Wr2[2*i],   ar0);
                az0 = ffma2(hv.x, Wz2[2*i],   az0);
                an0 = ffma2(hv.x, Wn2[2*i],   an0);
                ar1 = ffma2(hv.y, Wr2[2*i+1], ar1);
                az1 = ffma2(hv.y, Wz2[2*i+1], az1);
                an1 = ffma2(hv.y, Wn2[2*i+1], an1);
            }
            float arf = (f2lo(ar0) + f2hi(ar0)) + (f2lo(ar1) + f2hi(ar1));
            float azf = (f2lo(az0) + f2hi(az0)) + (f2lo(az1) + f2hi(az1));
            float anf = (f2lo(an0) + f2hi(an0)) + (f2lo(an1) + f2hi(an1));

            float r = sigmoid_fast(xr1 + arf);
            float z = sigmoid_fast(xz1 + azf);
            float n = tanh_fast(fmaf(r, anf, xn1));
            h = fmaf(z, h - n, n);
            sh[wid][0][j] = h;
            xr1 = pr; xz1 = pz; xn1 = pn;
            __syncwarp();
        }
    }

    float v = h * W_head[j];
    #pragma unroll
    for (int o = 16; o > 0; o >>= 1)
        v += __shfl_xor_sync(0xffffffffu, v, o);
    if (j == 0)
        out[row] = sigmoid_fast(v + b_head[0]);
}

extern "C" void kernel_launch(void* const* d_in, const int* in_sizes, int n_in,
                              void* d_out, int out_size)
{
    const float* x      = (const float*)d_in[0];
    const float* W_ih   = (const float*)d_in[1];
    const float* W_hh   = (const float*)d_in[2];
    const float* b_ih   = (const float*)d_in[3];
    const float* b_hh   = (const float*)d_in[4];
    const float* W_head = (const float*)d_in[5];
    const float* b_head = (const float*)d_in[6];
    float* out = (float*)d_out;

    float* xg;
    cudaGetSymbolAddress((void**)&xg, g_xg);

    cudaFuncSetAttribute(proj_kernel, cudaFuncAttributeMaxDynamicSharedMemorySize, SMEM_P1);
    proj_kernel<<<(B_ * T_) / PM, 256, SMEM_P1>>>(x, W_ih, b_ih, xg);
    gru_kernel<<<B_ / WARPS_P2, 32 * WARPS_P2>>>(xg, W_hh, b_hh, W_head, b_head, out);
}

// round 14
// speedup vs baseline: 1.1681x; 1.1681x over previous
#include <cuda_runtime.h>
#include <cuda_bf16.h>
#include <cstdint>

#define B_ 2048
#define T_ 256
#define F_ 64
#define H_ 32
#define G_ 96

// scratch: xg[B*T][96] fp32 (201 MB)
__device__ float g_xg[(size_t)B_ * T_ * G_];

__device__ __forceinline__ uint32_t smem_u32(const void* p) {
    uint32_t a;
    asm("{ .reg .u64 t; cvta.to.shared.u64 t, %1; cvt.u32.u64 %0, t; }" : "=r"(a) : "l"(p));
    return a;
}
__device__ __forceinline__ float tanh_fast(float v) {
    float y; asm("tanh.approx.f32 %0, %1;" : "=f"(y) : "f"(v)); return y;
}
__device__ __forceinline__ float sigmoid_fast(float a) {
    return fmaf(tanh_fast(0.5f * a), 0.5f, 0.5f);
}
__device__ __forceinline__ uint64_t ffma2(uint64_t a, uint64_t b, uint64_t c) {
    uint64_t d;
    asm("fma.rn.f32x2 %0, %1, %2, %3;" : "=l"(d) : "l"(a), "l"(b), "l"(c));
    return d;
}
__device__ __forceinline__ float f2lo(uint64_t v) { return __uint_as_float((uint32_t)v); }
__device__ __forceinline__ float f2hi(uint64_t v) { return __uint_as_float((uint32_t)(v >> 32)); }
__device__ __forceinline__ uint32_t pack_bf16(float a, float b) {
    __nv_bfloat162 t = __floats2bfloat162_rn(a, b);
    return *reinterpret_cast<uint32_t*>(&t);
}

// ================= Phase 1: xg = x @ W_ih^T + b_ih  (mma.sync bf16, 3-pass split) ===========
#define PM 128
#define AROW 144
#define AH_OFF 0
#define AL_OFF (PM * AROW)
#define BH_OFF (2 * PM * AROW)
#define BL_OFF (BH_OFF + G_ * AROW)
#define SMEM_P1 (BL_OFF + G_ * AROW)
#define STRIDE_ST 100

__device__ __forceinline__ void mma_bf16(float* d, uint32_t a0, uint32_t a1, uint32_t a2,
                                         uint32_t a3, uint32_t b0, uint32_t b1) {
    asm("mma.sync.aligned.m16n8k16.row.col.f32.bf16.bf16.f32 "
        "{%0,%1,%2,%3}, {%4,%5,%6,%7}, {%8,%9}, {%0,%1,%2,%3};"
        : "+f"(d[0]), "+f"(d[1]), "+f"(d[2]), "+f"(d[3])
        : "r"(a0), "r"(a1), "r"(a2), "r"(a3), "r"(b0), "r"(b1));
}
__device__ __forceinline__ void split4(float4 v, uint2& hp, uint2& lp) {
    __nv_bfloat16 h0 = __float2bfloat16(v.x), h1 = __float2bfloat16(v.y);
    __nv_bfloat16 h2 = __float2bfloat16(v.z), h3 = __float2bfloat16(v.w);
    hp.x = pack_bf16(__bfloat162float(h0), __bfloat162float(h1));
    hp.y = pack_bf16(__bfloat162float(h2), __bfloat162float(h3));
    lp.x = pack_bf16(v.x - __bfloat162float(h0), v.y - __bfloat162float(h1));
    lp.y = pack_bf16(v.z - __bfloat162float(h2), v.w - __bfloat162float(h3));
}

__global__ __launch_bounds__(256, 3)
void proj_kernel(const float* __restrict__ x,
                 const float* __restrict__ W_ih,
                 const float* __restrict__ b_ih,
                 float* __restrict__ xg)
{
    extern __shared__ __align__(16) char dsm[];
    __shared__ __align__(16) float sbias[G_];

    const int tid  = threadIdx.x;
    const int wid  = tid >> 5;
    const int lane = tid & 31;
    const int g    = lane >> 2;
    const int tg   = lane & 3;
    const size_t base = (size_t)blockIdx.x * PM;

    {
        const float4* xin = reinterpret_cast<const float4*>(x + base * F_);
        #pragma unroll
        for (int it = 0; it < PM * F_ / 4 / 256; it++) {
            int i = tid + it * 256;
            float4 v = xin[i];
            int row = i >> 4, c4 = i & 15;
            uint2 hp, lp; split4(v, hp, lp);
            uint32_t off = row * AROW + c4 * 8;
            *reinterpret_cast<uint2*>(dsm + AH_OFF + off) = hp;
            *reinterpret_cast<uint2*>(dsm + AL_OFF + off) = lp;
        }
    }
    {
        const float4* win = reinterpret_cast<const float4*>(W_ih);
        #pragma unroll
        for (int it = 0; it < G_ * F_ / 4 / 256; it++) {
            int i = tid + it * 256;
            float4 v = win[i];
            int row = i >> 4, c4 = i & 15;
            uint2 hp, lp; split4(v, hp, lp);
            uint32_t off = row * AROW + c4 * 8;
            *reinterpret_cast<uint2*>(dsm + BH_OFF + off) = hp;
            *reinterpret_cast<uint2*>(dsm + BL_OFF + off) = lp;
        }
    }
    if (tid < G_) sbias[tid] = b_ih[tid];
    __syncthreads();

    const int m0 = wid * 16;
    float acc[12][4];
    #pragma unroll
    for (int n = 0; n < 12; n++)
        #pragma unroll
        for (int q = 0; q < 4; q++) acc[n][q] = 0.f;

    const uint32_t arow0 = (m0 + g) * AROW;
    const uint32_t arow1 = (m0 + g + 8) * AROW;

    #pragma unroll
    for (int k = 0; k < 4; k++) {
        const uint32_t c0 = (k * 16 + 2 * tg) * 2;
        const uint32_t c1 = c0 + 16;
        uint32_t ah0 = *reinterpret_cast<const uint32_t*>(dsm + AH_OFF + arow0 + c0);
        uint32_t ah1 = *reinterpret_cast<const uint32_t*>(dsm + AH_OFF + arow1 + c0);
        uint32_t ah2 = *reinterpret_cast<const uint32_t*>(dsm + AH_OFF + arow0 + c1);
        uint32_t ah3 = *reinterpret_cast<const uint32_t*>(dsm + AH_OFF + arow1 + c1);
        uint32_t al0 = *reinterpret_cast<const uint32_t*>(dsm + AL_OFF + arow0 + c0);
        uint32_t al1 = *reinterpret_cast<const uint32_t*>(dsm + AL_OFF + arow1 + c0);
        uint32_t al2 = *reinterpret_cast<const uint32_t*>(dsm + AL_OFF + arow0 + c1);
        uint32_t al3 = *reinterpret_cast<const uint32_t*>(dsm + AL_OFF + arow1 + c1);
        #pragma unroll
        for (int n = 0; n < 12; n++) {
            const uint32_t brow = (n * 8 + g) * AROW;
            uint32_t bh0 = *reinterpret_cast<const uint32_t*>(dsm + BH_OFF + brow + c0);
            uint32_t bh1 = *reinterpret_cast<const uint32_t*>(dsm + BH_OFF + brow + c1);
            uint32_t bl0 = *reinterpret_cast<const uint32_t*>(dsm + BL_OFF + brow + c0);
            uint32_t bl1 = *reinterpret_cast<const uint32_t*>(dsm + BL_OFF + brow + c1);
            mma_bf16(acc[n], ah0, ah1, ah2, ah3, bh0, bh1);
            mma_bf16(acc[n], ah0, ah1, ah2, ah3, bl0, bl1);
            mma_bf16(acc[n], al0, al1, al2, al3, bh0, bh1);
        }
    }
    __syncthreads();

    float* stage = reinterpret_cast<float*>(dsm);
    {
        #pragma unroll
        for (int n = 0; n < 12; n++) {
            int c = n * 8 + 2 * tg;
            float2* p0 = reinterpret_cast<float2*>(&stage[(m0 + g) * STRIDE_ST + c]);
            float2* p1 = reinterpret_cast<float2*>(&stage[(m0 + g + 8) * STRIDE_ST + c]);
            *p0 = make_float2(acc[n][0], acc[n][1]);
            *p1 = make_float2(acc[n][2], acc[n][3]);
        }
    }
    __syncthreads();

    {
        float4* outp = reinterpret_cast<float4*>(xg + base * G_);
        #pragma unroll
        for (int it = 0; it < PM * G_ / 4 / 256; it++) {
            int i = tid + it * 256;
            int e = 4 * i;
            int r = e / G_, c = e % G_;
            float4 bb = *reinterpret_cast<const float4*>(&sbias[c]);
            const float* sp = &stage[r * STRIDE_ST + c];
            float4 v;
            v.x = sp[0] + bb.x; v.y = sp[1] + bb.y;
            v.z = sp[2] + bb.z; v.w = sp[3] + bb.w;
            outp[i] = v;
        }
    }
}

// ========== Phase 2: recurrence — 2 rows per warp, cp.async ring, f32x2 ==========
// CTA = 2 warps (64 thr). Warp handles batch rows 2*gw and 2*gw+1 (gw = global warp id).
// Weights (96 regs) shared across both rows; 12 interleaved FFMA2 chains.
#define WARPS_P2 2
#define PF 7

__global__ __launch_bounds__(64, 6)
void gru_kernel(const float* __restrict__ xg,
                const float* __restrict__ W_hh,
                const float* __restrict__ b_hh,
                const float* __restrict__ W_head,
                const float* __restrict__ b_head,
                float* __restrict__ out)
{
    // ring[warp][slot][row][gate]
    __shared__ __align__(16) float ring[WARPS_P2][8][2][G_];
    __shared__ __align__(16) float sh[WARPS_P2][2][2][H_];   // [warp][buf][row][unit]

    const int wid = threadIdx.x >> 5;
    const int j   = threadIdx.x & 31;
    const int gw  = blockIdx.x * WARPS_P2 + wid;
    const int row0 = gw * 2;

    // shared per-lane recurrent weights (f32x2 pairs)
    uint64_t Wr2[H_ / 2], Wz2[H_ / 2], Wn2[H_ / 2];
    {
        const ulonglong2* pr = reinterpret_cast<const ulonglong2*>(W_hh + (j)          * H_);
        const ulonglong2* pz = reinterpret_cast<const ulonglong2*>(W_hh + (H_ + j)     * H_);
        const ulonglong2* pn = reinterpret_cast<const ulonglong2*>(W_hh + (2 * H_ + j) * H_);
        #pragma unroll
        for (int i = 0; i < H_ / 4; i++) {
            ulonglong2 a = pr[i], b = pz[i], c = pn[i];
            Wr2[2*i] = a.x; Wr2[2*i+1] = a.y;
            Wz2[2*i] = b.x; Wz2[2*i+1] = b.y;
            Wn2[2*i] = c.x; Wn2[2*i+1] = c.y;
        }
    }
    const uint64_t br2 = (uint64_t)__float_as_uint(b_hh[j]);
    const uint64_t bz2 = (uint64_t)__float_as_uint(b_hh[H_ + j]);
    const uint64_t bn2 = (uint64_t)__float_as_uint(b_hh[2 * H_ + j]);

    const float* xp0 = xg + (size_t)row0 * T_ * G_;        // row0 stream
    const float* xp1 = xp0 + (size_t)T_ * G_;              // row1 stream
    const uint32_t rb = smem_u32(&ring[wid][0][0][0]);

    // preload ring slots 0..PF-1: lanes 0-23 copy 16B for each row
    #pragma unroll
    for (int p = 0; p < PF; p++) {
        if (j < 24) {
            uint32_t dst0 = rb + (uint32_t)p * (2 * G_ * 4) + j * 16;
            uint32_t dst1 = dst0 + G_ * 4;
            const float* s0 = xp0 + p * G_ + j * 4;
            const float* s1 = xp1 + p * G_ + j * 4;
            asm volatile("cp.async.cg.shared.global [%0], [%1], 16;" :: "r"(dst0), "l"(s0));
            asm volatile("cp.async.cg.shared.global [%0], [%1], 16;" :: "r"(dst1), "l"(s1));
        }
        asm volatile("cp.async.commit_group;" ::: "memory");
    }

    sh[wid][0][0][j] = 0.f;
    sh[wid][0][1][j] = 0.f;
    float h0 = 0.f, h1 = 0.f;
    __syncwarp();

    #pragma unroll 1
    for (int t = 0; t < T_; t++) {
        {
            int ft = t + PF;
            if (ft < T_ && j < 24) {
                uint32_t dst0 = rb + (uint32_t)(ft & 7) * (2 * G_ * 4) + j * 16;
                uint32_t dst1 = dst0 + G_ * 4;
                const float* s0 = xp0 + (size_t)ft * G_ + j * 4;
                const float* s1 = xp1 + (size_t)ft * G_ + j * 4;
                asm volatile("cp.async.cg.shared.global [%0], [%1], 16;" :: "r"(dst0), "l"(s0));
                asm volatile("cp.async.cg.shared.global [%0], [%1], 16;" :: "r"(dst1), "l"(s1));
            }
            asm volatile("cp.async.commit_group;" ::: "memory");
            asm volatile("cp.async.wait_group 6;" ::: "memory");
            __syncwarp();
        }

        const float* xs0 = &ring[wid][t & 7][0][0];
        const float* xs1 = &ring[wid][t & 7][1][0];
        float xr0 = xs0[j], xz0 = xs0[H_ + j], xn0 = xs0[2 * H_ + j];
        float xr1 = xs1[j], xz1 = xs1[H_ + j], xn1 = xs1[2 * H_ + j];

        const ulonglong2* hp0 = reinterpret_cast<const ulonglong2*>(sh[wid][t & 1][0]);
        const ulonglong2* hp1 = reinterpret_cast<const ulonglong2*>(sh[wid][t & 1][1]);

        // 12 interleaved chains (6 per row, depth 8)
        uint64_t r0a = br2, r0b = 0ull, z0a = bz2, z0b = 0ull, n0a = bn2, n0b = 0ull;
        uint64_t r1a = br2, r1b = 0ull, z1a = bz2, z1b = 0ull, n1a = bn2, n1b = 0ull;
        #pragma unroll
        for (int i = 0; i < H_ / 4; i++) {
            ulonglong2 hv0 = hp0[i];
            ulonglong2 hv1 = hp1[i];
            r0a = ffma2(hv0.x, Wr2[2*i],   r0a);
            z0a = ffma2(hv0.x, Wz2[2*i],   z0a);
            n0a = ffma2(hv0.x, Wn2[2*i],   n0a);
            r1a = ffma2(hv1.x, Wr2[2*i],   r1a);
            z1a = ffma2(hv1.x, Wz2[2*i],   z1a);
            n1a = ffma2(hv1.x, Wn2[2*i],   n1a);
            r0b = ffma2(hv0.y, Wr2[2*i+1], r0b);
            z0b = ffma2(hv0.y, Wz2[2*i+1], z0b);
            n0b = ffma2(hv0.y, Wn2[2*i+1], n0b);
            r1b = ffma2(hv1.y, Wr2[2*i+1], r1b);
            z1b = ffma2(hv1.y, Wz2[2*i+1], z1b);
            n1b = ffma2(hv1.y, Wn2[2*i+1], n1b);
        }
        float arf0 = (f2lo(r0a) + f2hi(r0a)) + (f2lo(r0b) + f2hi(r0b));
        float azf0 = (f2lo(z0a) + f2hi(z0a)) + (f2lo(z0b) + f2hi(z0b));
        float anf0 = (f2lo(n0a) + f2hi(n0a)) + (f2lo(n0b) + f2hi(n0b));
        float arf1 = (f2lo(r1a) + f2hi(r1a)) + (f2lo(r1b) + f2hi(r1b));
        float azf1 = (f2lo(z1a) + f2hi(z1a)) + (f2lo(z1b) + f2hi(z1b));
        float anf1 = (f2lo(n1a) + f2hi(n1a)) + (f2lo(n1b) + f2hi(n1b));

        float r0 = sigmoid_fast(xr0 + arf0);
        float z0 = sigmoid_fast(xz0 + azf0);
        float n0 = tanh_fast(fmaf(r0, anf0, xn0));
        h0 = fmaf(z0, h0 - n0, n0);

        float r1 = sigmoid_fast(xr1 + arf1);
        float z1 = sigmoid_fast(xz1 + azf1);
        float n1 = tanh_fast(fmaf(r1, anf1, xn1));
        h1 = fmaf(z1, h1 - n1, n1);

        sh[wid][(t + 1) & 1][0][j] = h0;
        sh[wid][(t + 1) & 1][1][j] = h1;
        __syncwarp();
    }

    // head for both rows
    float wv = W_head[j];
    float v0 = h0 * wv;
    float v1 = h1 * wv;
    #pragma unroll
    for (int o = 16; o > 0; o >>= 1) {
        v0 += __shfl_xor_sync(0xffffffffu, v0, o);
        v1 += __shfl_xor_sync(0xffffffffu, v1, o);
    }
    if (j == 0) {
        float bh = b_head[0];
        out[row0]     = sigmoid_fast(v0 + bh);
        out[row0 + 1] = sigmoid_fast(v1 + bh);
    }
}

extern "C" void kernel_launch(void* const* d_in, const int* in_sizes, int n_in,
                              void* d_out, int out_size)
{
    const float* x      = (const float*)d_in[0];
    const float* W_ih   = (const float*)d_in[1];
    const float* W_hh   = (const float*)d_in[2];
    const float* b_ih   = (const float*)d_in[3];
    const float* b_hh   = (const float*)d_in[4];
    const float* W_head = (const float*)d_in[5];
    const float* b_head = (const float*)d_in[6];
    float* out = (float*)d_out;

    float* xg;
    cudaGetSymbolAddress((void**)&xg, g_xg);

    cudaFuncSetAttribute(proj_kernel, cudaFuncAttributeMaxDynamicSharedMemorySize, SMEM_P1);
    proj_kernel<<<(B_ * T_) / PM, 256, SMEM_P1>>>(x, W_ih, b_ih, xg);
    gru_kernel<<<B_ / (WARPS_P2 * 2), 32 * WARPS_P2>>>(xg, W_hh, b_hh, W_head, b_head, out);
}

// round 15
// speedup vs baseline: 1.1782x; 1.0087x over previous
#include <cuda_runtime.h>
#include <cuda_bf16.h>
#include <cstdint>

#define B_ 2048
#define T_ 256
#define F_ 64
#define H_ 32
#define G_ 96

// scratch: xg[B*T][96] fp32 (201 MB)
__device__ float g_xg[(size_t)B_ * T_ * G_];

__device__ __forceinline__ uint32_t smem_u32(const void* p) {
    uint32_t a;
    asm("{ .reg .u64 t; cvta.to.shared.u64 t, %1; cvt.u32.u64 %0, t; }" : "=r"(a) : "l"(p));
    return a;
}
__device__ __forceinline__ float tanh_fast(float v) {
    float y; asm("tanh.approx.f32 %0, %1;" : "=f"(y) : "f"(v)); return y;
}
__device__ __forceinline__ float sigmoid_fast(float a) {
    return fmaf(tanh_fast(0.5f * a), 0.5f, 0.5f);
}
__device__ __forceinline__ uint64_t ffma2(uint64_t a, uint64_t b, uint64_t c) {
    uint64_t d;
    asm("fma.rn.f32x2 %0, %1, %2, %3;" : "=l"(d) : "l"(a), "l"(b), "l"(c));
    return d;
}
__device__ __forceinline__ float f2lo(uint64_t v) { return __uint_as_float((uint32_t)v); }
__device__ __forceinline__ float f2hi(uint64_t v) { return __uint_as_float((uint32_t)(v >> 32)); }
__device__ __forceinline__ uint32_t pack_bf16(float a, float b) {
    __nv_bfloat162 t = __floats2bfloat162_rn(a, b);
    return *reinterpret_cast<uint32_t*>(&t);
}

// ================= Phase 1: xg = x @ W_ih^T + b_ih  (mma.sync bf16, 3-pass split) ===========
#define PM 128
#define AROW 144
#define AH_OFF 0
#define AL_OFF (PM * AROW)
#define BH_OFF (2 * PM * AROW)
#define BL_OFF (BH_OFF + G_ * AROW)
#define SMEM_P1 (BL_OFF + G_ * AROW)
#define STRIDE_ST 100

__device__ __forceinline__ void mma_bf16(float* d, uint32_t a0, uint32_t a1, uint32_t a2,
                                         uint32_t a3, uint32_t b0, uint32_t b1) {
    asm("mma.sync.aligned.m16n8k16.row.col.f32.bf16.bf16.f32 "
        "{%0,%1,%2,%3}, {%4,%5,%6,%7}, {%8,%9}, {%0,%1,%2,%3};"
        : "+f"(d[0]), "+f"(d[1]), "+f"(d[2]), "+f"(d[3])
        : "r"(a0), "r"(a1), "r"(a2), "r"(a3), "r"(b0), "r"(b1));
}
__device__ __forceinline__ void split4(float4 v, uint2& hp, uint2& lp) {
    __nv_bfloat16 h0 = __float2bfloat16(v.x), h1 = __float2bfloat16(v.y);
    __nv_bfloat16 h2 = __float2bfloat16(v.z), h3 = __float2bfloat16(v.w);
    hp.x = pack_bf16(__bfloat162float(h0), __bfloat162float(h1));
    hp.y = pack_bf16(__bfloat162float(h2), __bfloat162float(h3));
    lp.x = pack_bf16(v.x - __bfloat162float(h0), v.y - __bfloat162float(h1));
    lp.y = pack_bf16(v.z - __bfloat162float(h2), v.w - __bfloat162float(h3));
}

__global__ __launch_bounds__(256, 3)
void proj_kernel(const float* __restrict__ x,
                 const float* __restrict__ W_ih,
                 const float* __restrict__ b_ih,
                 float* __restrict__ xg)
{
    extern __shared__ __align__(16) char dsm[];
    __shared__ __align__(16) float sbias[G_];

    const int tid  = threadIdx.x;
    const int wid  = tid >> 5;
    const int lane = tid & 31;
    const int g    = lane >> 2;
    const int tg   = lane & 3;
    const size_t base = (size_t)blockIdx.x * PM;

    {
        const float4* xin = reinterpret_cast<const float4*>(x + base * F_);
        #pragma unroll
        for (int it = 0; it < PM * F_ / 4 / 256; it++) {
            int i = tid + it * 256;
            float4 v = xin[i];
            int row = i >> 4, c4 = i & 15;
            uint2 hp, lp; split4(v, hp, lp);
            uint32_t off = row * AROW + c4 * 8;
            *reinterpret_cast<uint2*>(dsm + AH_OFF + off) = hp;
            *reinterpret_cast<uint2*>(dsm + AL_OFF + off) = lp;
        }
    }
    {
        const float4* win = reinterpret_cast<const float4*>(W_ih);
        #pragma unroll
        for (int it = 0; it < G_ * F_ / 4 / 256; it++) {
            int i = tid + it * 256;
            float4 v = win[i];
            int row = i >> 4, c4 = i & 15;
            uint2 hp, lp; split4(v, hp, lp);
            uint32_t off = row * AROW + c4 * 8;
            *reinterpret_cast<uint2*>(dsm + BH_OFF + off) = hp;
            *reinterpret_cast<uint2*>(dsm + BL_OFF + off) = lp;
        }
    }
    if (tid < G_) sbias[tid] = b_ih[tid];
    __syncthreads();

    const int m0 = wid * 16;
    float acc[12][4];
    #pragma unroll
    for (int n = 0; n < 12; n++)
        #pragma unroll
        for (int q = 0; q < 4; q++) acc[n][q] = 0.f;

    const uint32_t arow0 = (m0 + g) * AROW;
    const uint32_t arow1 = (m0 + g + 8) * AROW;

    #pragma unroll
    for (int k = 0; k < 4; k++) {
        const uint32_t c0 = (k * 16 + 2 * tg) * 2;
        const uint32_t c1 = c0 + 16;
        uint32_t ah0 = *reinterpret_cast<const uint32_t*>(dsm + AH_OFF + arow0 + c0);
        uint32_t ah1 = *reinterpret_cast<const uint32_t*>(dsm + AH_OFF + arow1 + c0);
        uint32_t ah2 = *reinterpret_cast<const uint32_t*>(dsm + AH_OFF + arow0 + c1);
        uint32_t ah3 = *reinterpret_cast<const uint32_t*>(dsm + AH_OFF + arow1 + c1);
        uint32_t al0 = *reinterpret_cast<const uint32_t*>(dsm + AL_OFF + arow0 + c0);
        uint32_t al1 = *reinterpret_cast<const uint32_t*>(dsm + AL_OFF + arow1 + c0);
        uint32_t al2 = *reinterpret_cast<const uint32_t*>(dsm + AL_OFF + arow0 + c1);
        uint32_t al3 = *reinterpret_cast<const uint32_t*>(dsm + AL_OFF + arow1 + c1);
        #pragma unroll
        for (int n = 0; n < 12; n++) {
            const uint32_t brow = (n * 8 + g) * AROW;
            uint32_t bh0 = *reinterpret_cast<const uint32_t*>(dsm + BH_OFF + brow + c0);
            uint32_t bh1 = *reinterpret_cast<const uint32_t*>(dsm + BH_OFF + brow + c1);
            uint32_t bl0 = *reinterpret_cast<const uint32_t*>(dsm + BL_OFF + brow + c0);
            uint32_t bl1 = *reinterpret_cast<const uint32_t*>(dsm + BL_OFF + brow + c1);
            mma_bf16(acc[n], ah0, ah1, ah2, ah3, bh0, bh1);
            mma_bf16(acc[n], ah0, ah1, ah2, ah3, bl0, bl1);
            mma_bf16(acc[n], al0, al1, al2, al3, bh0, bh1);
        }
    }
    __syncthreads();

    float* stage = reinterpret_cast<float*>(dsm);
    {
        #pragma unroll
        for (int n = 0; n < 12; n++) {
            int c = n * 8 + 2 * tg;
            float2* p0 = reinterpret_cast<float2*>(&stage[(m0 + g) * STRIDE_ST + c]);
            float2* p1 = reinterpret_cast<float2*>(&stage[(m0 + g + 8) * STRIDE_ST + c]);
            *p0 = make_float2(acc[n][0], acc[n][1]);
            *p1 = make_float2(acc[n][2], acc[n][3]);
        }
    }
    __syncthreads();

    {
        float4* outp = reinterpret_cast<float4*>(xg + base * G_);
        #pragma unroll
        for (int it = 0; it < PM * G_ / 4 / 256; it++) {
            int i = tid + it * 256;
            int e = 4 * i;
            int r = e / G_, c = e % G_;
            float4 bb = *reinterpret_cast<const float4*>(&sbias[c]);
            const float* sp = &stage[r * STRIDE_ST + c];
            float4 v;
            v.x = sp[0] + bb.x; v.y = sp[1] + bb.y;
            v.z = sp[2] + bb.z; v.w = sp[3] + bb.w;
            outp[i] = v;
        }
    }
}

// ========== Phase 2: recurrence — 4 rows per warp, 1-warp CTAs, cp.async ring ==========
#define ROWS 4
#define NSLOT 8
#define PF 7
#define SLOTB (ROWS * G_ * 4)     // 1536 bytes per ring slot

__global__ __launch_bounds__(32, 8)
void gru_kernel(const float* __restrict__ xg,
                const float* __restrict__ W_hh,
                const float* __restrict__ b_hh,
                const float* __restrict__ W_head,
                const float* __restrict__ b_head,
                float* __restrict__ out)
{
    __shared__ __align__(16) float ring[NSLOT][ROWS][G_];   // 12 KB
    __shared__ __align__(16) float sh[2][ROWS][H_];         // 1 KB

    const int j    = threadIdx.x & 31;
    const int row0 = blockIdx.x * ROWS;

    // shared per-lane recurrent weights (f32x2 pairs)
    uint64_t Wr2[H_ / 2], Wz2[H_ / 2], Wn2[H_ / 2];
    {
        const ulonglong2* pr = reinterpret_cast<const ulonglong2*>(W_hh + (j)          * H_);
        const ulonglong2* pz = reinterpret_cast<const ulonglong2*>(W_hh + (H_ + j)     * H_);
        const ulonglong2* pn = reinterpret_cast<const ulonglong2*>(W_hh + (2 * H_ + j) * H_);
        #pragma unroll
        for (int i = 0; i < H_ / 4; i++) {
            ulonglong2 a = pr[i], b = pz[i], c = pn[i];
            Wr2[2*i] = a.x; Wr2[2*i+1] = a.y;
            Wz2[2*i] = b.x; Wz2[2*i+1] = b.y;
            Wn2[2*i] = c.x; Wn2[2*i+1] = c.y;
        }
    }
    const uint64_t br2 = (uint64_t)__float_as_uint(b_hh[j]);
    const uint64_t bz2 = (uint64_t)__float_as_uint(b_hh[H_ + j]);
    const uint64_t bn2 = (uint64_t)__float_as_uint(b_hh[2 * H_ + j]);

    // per-lane cp.async source bases: 3 chunks per lane, chunk id = j + 32*c.
    // chunk ch covers slot bytes [ch*16, ch*16+16) = row (ch/24), row-offset (ch%24)*16.
    const float* srcb[3];
    uint32_t     dsto[3];
    #pragma unroll
    for (int c = 0; c < 3; c++) {
        int ch = j + 32 * c;
        int r  = ch / 24;
        int wo = ch % 24;
        srcb[c] = xg + ((size_t)(row0 + r) * T_) * G_ + wo * 4;
        dsto[c] = (uint32_t)ch * 16;
    }
    const uint32_t rb = smem_u32(&ring[0][0][0]);

    // preload slots 0..PF-1
    #pragma unroll
    for (int p = 0; p < PF; p++) {
        #pragma unroll
        for (int c = 0; c < 3; c++) {
            uint32_t dst = rb + (uint32_t)p * SLOTB + dsto[c];
            const float* src = srcb[c] + (size_t)p * G_;
            asm volatile("cp.async.cg.shared.global [%0], [%1], 16;" :: "r"(dst), "l"(src));
        }
        asm volatile("cp.async.commit_group;" ::: "memory");
    }

    #pragma unroll
    for (int r = 0; r < ROWS; r++) sh[0][r][j] = 0.f;
    float h[ROWS];
    #pragma unroll
    for (int r = 0; r < ROWS; r++) h[r] = 0.f;
    __syncwarp();

    #pragma unroll 1
    for (int t = 0; t < T_; t++) {
        // prefetch slot t+PF
        {
            int ft = t + PF;
            if (ft < T_) {
                #pragma unroll
                for (int c = 0; c < 3; c++) {
                    uint32_t dst = rb + (uint32_t)(ft & (NSLOT - 1)) * SLOTB + dsto[c];
                    const float* src = srcb[c] + (size_t)ft * G_;
                    asm volatile("cp.async.cg.shared.global [%0], [%1], 16;" :: "r"(dst), "l"(src));
                }
            }
            asm volatile("cp.async.commit_group;" ::: "memory");
            asm volatile("cp.async.wait_group 6;" ::: "memory");
            __syncwarp();
        }

        // gate inputs for all rows
        float xr[ROWS], xz[ROWS], xn[ROWS];
        #pragma unroll
        for (int r = 0; r < ROWS; r++) {
            const float* xs = &ring[t & (NSLOT - 1)][r][0];
            xr[r] = xs[j]; xz[r] = xs[H_ + j]; xn[r] = xs[2 * H_ + j];
        }

        // 12 independent FFMA2 chains (3 gates x 4 rows, depth 16)
        uint64_t ar[ROWS], az[ROWS], an[ROWS];
        #pragma unroll
        for (int r = 0; r < ROWS; r++) { ar[r] = br2; az[r] = bz2; an[r] = bn2; }

        const ulonglong2* hp[ROWS];
        #pragma unroll
        for (int r = 0; r < ROWS; r++)
            hp[r] = reinterpret_cast<const ulonglong2*>(sh[t & 1][r]);

        #pragma unroll
        for (int i = 0; i < H_ / 4; i++) {
            #pragma unroll
            for (int r = 0; r < ROWS; r++) {
                ulonglong2 hv = hp[r][i];
                ar[r] = ffma2(hv.x, Wr2[2*i],   ar[r]);
                az[r] = ffma2(hv.x, Wz2[2*i],   az[r]);
                an[r] = ffma2(hv.x, Wn2[2*i],   an[r]);
                ar[r] = ffma2(hv.y, Wr2[2*i+1], ar[r]);
                az[r] = ffma2(hv.y, Wz2[2*i+1], az[r]);
                an[r] = ffma2(hv.y, Wn2[2*i+1], an[r]);
            }
        }

        #pragma unroll
        for (int r = 0; r < ROWS; r++) {
            float arf = f2lo(ar[r]) + f2hi(ar[r]);
            float azf = f2lo(az[r]) + f2hi(az[r]);
            float anf = f2lo(an[r]) + f2hi(an[r]);
            float rg = sigmoid_fast(xr[r] + arf);
            float zg = sigmoid_fast(xz[r] + azf);
            float ng = tanh_fast(fmaf(rg, anf, xn[r]));
            h[r] = fmaf(zg, h[r] - ng, ng);
            sh[(t + 1) & 1][r][j] = h[r];
        }
        __syncwarp();
    }

    // head for all rows
    float wv = W_head[j];
    float v[ROWS];
    #pragma unroll
    for (int r = 0; r < ROWS; r++) v[r] = h[r] * wv;
    #pragma unroll
    for (int o = 16; o > 0; o >>= 1) {
        #pragma unroll
        for (int r = 0; r < ROWS; r++)
            v[r] += __shfl_xor_sync(0xffffffffu, v[r], o);
    }
    if (j == 0) {
        float bh = b_head[0];
        #pragma unroll
        for (int r = 0; r < ROWS; r++)
            out[row0 + r] = sigmoid_fast(v[r] + bh);
    }
}

extern "C" void kernel_launch(void* const* d_in, const int* in_sizes, int n_in,
                              void* d_out, int out_size)
{
    const float* x      = (const float*)d_in[0];
    const float* W_ih   = (const float*)d_in[1];
    const float* W_hh   = (const float*)d_in[2];
    const float* b_ih   = (const float*)d_in[3];
    const float* b_hh   = (const float*)d_in[4];
    const float* W_head = (const float*)d_in[5];
    const float* b_head = (const float*)d_in[6];
    float* out = (float*)d_out;

    float* xg;
    cudaGetSymbolAddress((void**)&xg, g_xg);

    cudaFuncSetAttribute(proj_kernel, cudaFuncAttributeMaxDynamicSharedMemorySize, SMEM_P1);
    proj_kernel<<<(B_ * T_) / PM, 256, SMEM_P1>>>(x, W_ih, b_ih, xg);
    gru_kernel<<<B_ / ROWS, 32>>>(xg, W_hh, b_hh, W_head, b_head, out);
}